// round 14
// baseline (speedup 1.0000x reference)
#include <cuda_runtime.h>
#include <cuda_fp16.h>
#include <math.h>
#include <stdint.h>

#define NPIX  16384   // 4*64*64
#define CDIM  128

// Scratch (device globals: no allocations allowed)
__device__ uint32_t g_qh[NPIX * 64];   // half2-packed q
__device__ uint32_t g_kh[NPIX * 64];   // half2-packed k
__device__ uint32_t g_vh[NPIX * 64];   // half2-packed v
__device__ uint32_t g_wpack[64 * 128]; // proj W: [kpair][n] half2(W[2kp][n],W[2kp+1][n])

// ---------------- fp16 mma helpers ----------------
__device__ __forceinline__ uint32_t packh2(float x, float y) {
    uint32_t r;
    asm("{ .reg .f16 lo, hi;\n\t"
        "cvt.rn.f16.f32 lo, %1;\n\t"
        "cvt.rn.f16.f32 hi, %2;\n\t"
        "mov.b32 %0, {lo, hi}; }"
        : "=r"(r) : "f"(x), "f"(y));
    return r;
}
__device__ __forceinline__ __half2 as_h2(uint32_t w) {
    return *(__half2*)&w;
}
__device__ __forceinline__ uint32_t h2u(__half2 h) {
    return *(uint32_t*)&h;
}
__device__ __forceinline__ void mma_f16(float* d, const uint32_t* a,
                                        uint32_t b0, uint32_t b1) {
    asm volatile(
        "mma.sync.aligned.m16n8k16.row.col.f32.f16.f16.f32 "
        "{%0,%1,%2,%3}, {%4,%5,%6,%7}, {%8,%9}, {%0,%1,%2,%3};"
        : "+f"(d[0]), "+f"(d[1]), "+f"(d[2]), "+f"(d[3])
        : "r"(a[0]), "r"(a[1]), "r"(a[2]), "r"(a[3]), "r"(b0), "r"(b1));
}

// ---------------------------------------------------------------------------
// Fused QKV GEMM (unchanged, proven): 64-row tile x 3 slices per CTA,
// A fragments hoisted, B double-buffered. CTA 256 packs proj weights.
// ---------------------------------------------------------------------------
#define PA2 68
#define PB2 136
#define QKV_SMEM ((64 * PA2 + 2 * 64 * PB2) * 4)   // 87040 B

__global__ __launch_bounds__(256) void gemm_qkv(
    const float* __restrict__ x,       // [16384, 128]
    const float* __restrict__ wq,      // [128, 384]
    const float* __restrict__ wp,      // [128, 128]
    const float* __restrict__ bias)    // [384]
{
    const int bm  = blockIdx.x;
    const int tid = threadIdx.x;

    if (bm == 256) {
        for (int i = tid; i < 64 * 128; i += 256) {
            int kp = i >> 7;
            int n  = i & 127;
            g_wpack[i] = packh2(wp[(size_t)(2 * kp) * 128 + n],
                                wp[(size_t)(2 * kp + 1) * 128 + n]);
        }
        return;
    }

    extern __shared__ uint32_t smem_g[];
    uint32_t* As32 = smem_g;
    uint32_t* Bb0  = smem_g + 64 * PA2;
    uint32_t* Bb1  = smem_g + 64 * PA2 + 64 * PB2;

    const int lane = tid & 31;
    const int wrp  = tid >> 5;
    const int g    = lane >> 2;
    const int t    = lane & 3;
    const int wm   = wrp & 1;
    const int wn   = wrp >> 1;

    #pragma unroll
    for (int i = 0; i < 8; i++) {
        int f4 = tid + i * 256;
        int r  = f4 >> 5;
        int c4 = f4 & 31;
        float4 v = *(const float4*)&x[(size_t)(bm * 64 + r) * 128 + c4 * 4];
        As32[r * PA2 + c4 * 2 + 0] = packh2(v.x, v.y);
        As32[r * PA2 + c4 * 2 + 1] = packh2(v.z, v.w);
    }
    #pragma unroll
    for (int i = 0; i < 8; i++) {
        int idx = tid + i * 256;
        int kp  = idx >> 5;
        int ng  = idx & 31;
        float4 r0 = *(const float4*)&wq[(size_t)(2 * kp)     * 384 + ng * 4];
        float4 r1 = *(const float4*)&wq[(size_t)(2 * kp + 1) * 384 + ng * 4];
        uint4 p;
        p.x = packh2(r0.x, r1.x);
        p.y = packh2(r0.y, r1.y);
        p.z = packh2(r0.z, r1.z);
        p.w = packh2(r0.w, r1.w);
        *(uint4*)&Bb0[kp * PB2 + ng * 4] = p;
    }
    __syncthreads();

    uint32_t afr[8][2][4];
    #pragma unroll
    for (int ks = 0; ks < 8; ks++) {
        const int kp0 = ks * 8;
        #pragma unroll
        for (int mi = 0; mi < 2; mi++) {
            int rb = wm * 32 + mi * 16;
            afr[ks][mi][0] = As32[(rb + g)     * PA2 + kp0 + t];
            afr[ks][mi][1] = As32[(rb + g + 8) * PA2 + kp0 + t];
            afr[ks][mi][2] = As32[(rb + g)     * PA2 + kp0 + 4 + t];
            afr[ks][mi][3] = As32[(rb + g + 8) * PA2 + kp0 + 4 + t];
        }
    }

    #pragma unroll
    for (int s = 0; s < 3; s++) {
        if (s < 2) {
            uint32_t* Bn = ((s + 1) & 1) ? Bb1 : Bb0;
            #pragma unroll
            for (int i = 0; i < 8; i++) {
                int idx = tid + i * 256;
                int kp  = idx >> 5;
                int ng  = idx & 31;
                float4 r0 = *(const float4*)&wq[(size_t)(2 * kp)     * 384 + (s + 1) * 128 + ng * 4];
                float4 r1 = *(const float4*)&wq[(size_t)(2 * kp + 1) * 384 + (s + 1) * 128 + ng * 4];
                uint4 p;
                p.x = packh2(r0.x, r1.x);
                p.y = packh2(r0.y, r1.y);
                p.z = packh2(r0.z, r1.z);
                p.w = packh2(r0.w, r1.w);
                *(uint4*)&Bn[kp * PB2 + ng * 4] = p;
            }
        }

        const uint32_t* Bc = (s & 1) ? Bb1 : Bb0;
        float acc[2][4][4];
        #pragma unroll
        for (int i = 0; i < 2; i++)
            #pragma unroll
            for (int j = 0; j < 4; j++)
                #pragma unroll
                for (int c = 0; c < 4; c++) acc[i][j][c] = 0.f;

        #pragma unroll
        for (int ks = 0; ks < 8; ks++) {
            const int kp0 = ks * 8;
            #pragma unroll
            for (int ni = 0; ni < 4; ni++) {
                int cb = wn * 32 + ni * 8;
                uint32_t b0 = Bc[(kp0 + t)     * PB2 + cb + g];
                uint32_t b1 = Bc[(kp0 + 4 + t) * PB2 + cb + g];
                mma_f16(acc[0][ni], afr[ks][0], b0, b1);
                mma_f16(acc[1][ni], afr[ks][1], b0, b1);
            }
        }

        const float scale = (s == 0) ? 0.17677669529663688f : 1.0f;
        uint32_t* gd = (s == 0) ? g_qh : (s == 1) ? g_kh : g_vh;
        #pragma unroll
        for (int ni = 0; ni < 4; ni++) {
            int c  = wn * 32 + ni * 8 + t * 2;
            float b0 = bias[s * 128 + c];
            float b1 = bias[s * 128 + c + 1];
            #pragma unroll
            for (int mi = 0; mi < 2; mi++) {
                int r0 = bm * 64 + wm * 32 + mi * 16 + g;
                gd[(size_t)r0 * 64       + (c >> 1)] =
                    packh2((acc[mi][ni][0] + b0) * scale, (acc[mi][ni][1] + b1) * scale);
                gd[(size_t)(r0 + 8) * 64 + (c >> 1)] =
                    packh2((acc[mi][ni][2] + b0) * scale, (acc[mi][ni][3] + b1) * scale);
            }
        }

        if (s < 2) __syncthreads();
    }
}

// ---------------------------------------------------------------------------
// Fused natten + proj v4: scalar score pass + per-head tensor-core AV rounds.
// Hardened vs v3: owner P writes are whole-u32 half2 pairs (no u16 aliasing);
// V transpose uses __lows2half2/__highs2half2 intrinsics.
// smem (u32):
//   region1 @0     : K halo 196x68 (13328) -> P 64x108 (6912) + AT 64x68 @6912
//   region2 @13328 : VT 4x32x108 (13824)   -> BP 64x136 (8704)
//   l_s     @27152 : 256 floats
// ---------------------------------------------------------------------------
#define NSTRIDE4 17
#define R2OFF    13328
#define LSOFF    27152
#define NAT_U32  27408
#define NAT_SMEM (NAT_U32 * 4)    // 109632 B
#define PST      108              // P / VT row stride (u32)

__global__ __launch_bounds__(256, 2) void natten_proj_kernel(
    const float* __restrict__ rpb,
    const float* __restrict__ b_proj,
    float* __restrict__ out)
{
    extern __shared__ uint32_t smn[];
    uint4*    Ks4  = (uint4*)smn;
    uint32_t* P32  = smn;
    uint32_t* AT32 = smn + 6912;
    uint32_t* VT32 = smn + R2OFF;
    uint32_t* BP32 = smn + R2OFF;
    float*    l_s  = (float*)(smn + LSOFF);

    const int tid  = threadIdx.x;
    const int tile = blockIdx.x & 63;
    const int b    = blockIdx.x >> 6;
    const int Y    = (tile >> 3) * 8;
    const int X    = (tile & 7) * 8;

    const int hb = min(max(Y - 3, 0), 50);
    const int wb = min(max(X - 3, 0), 50);

    // ---- Stage K halo
    for (int i = tid; i < 196 * 16; i += 256) {
        int nb = i >> 4;
        int j  = i & 15;
        int ny = nb / 14;
        int nx = nb - ny * 14;
        int gp = (b * 64 + hb + ny) * 64 + wb + nx;
        Ks4[nb * NSTRIDE4 + j] = ((const uint4*)g_kh)[gp * 16 + j];
    }
    // ---- Stage V transposed: VT32[h*3456 + dim_local*PST + pair]
    //      = half2(V[nb=2p][dim], V[nb=2p+1][dim]) via half2 intrinsics
    {
        const uint4* gv4 = (const uint4*)g_vh;
        for (int it = tid; it < 98 * 4 * 4; it += 256) {
            int j4 = it & 3;
            int h  = (it >> 2) & 3;
            int p  = it >> 4;
            int nb0 = 2 * p;
            int ny0 = nb0 / 14, nx0 = nb0 - ny0 * 14;
            int ny1 = (nb0 + 1) / 14, nx1 = (nb0 + 1) - ny1 * 14;
            int pix0 = (b * 64 + hb + ny0) * 64 + wb + nx0;
            int pix1 = (b * 64 + hb + ny1) * 64 + wb + nx1;
            uint4 xa = gv4[pix0 * 16 + h * 4 + j4];
            uint4 xb = gv4[pix1 * 16 + h * 4 + j4];
            uint32_t base = h * 3456 + (j4 * 8) * PST + p;
            __half2 a0 = as_h2(xa.x), b0 = as_h2(xb.x);
            __half2 a1 = as_h2(xa.y), b1 = as_h2(xb.y);
            __half2 a2 = as_h2(xa.z), b2 = as_h2(xb.z);
            __half2 a3 = as_h2(xa.w), b3 = as_h2(xb.w);
            VT32[base + 0 * PST] = h2u(__lows2half2(a0, b0));
            VT32[base + 1 * PST] = h2u(__highs2half2(a0, b0));
            VT32[base + 2 * PST] = h2u(__lows2half2(a1, b1));
            VT32[base + 3 * PST] = h2u(__highs2half2(a1, b1));
            VT32[base + 4 * PST] = h2u(__lows2half2(a2, b2));
            VT32[base + 5 * PST] = h2u(__highs2half2(a2, b2));
            VT32[base + 6 * PST] = h2u(__lows2half2(a3, b3));
            VT32[base + 7 * PST] = h2u(__highs2half2(a3, b3));
        }
        // zero pad pairs 98..103
        for (int i = tid; i < 4 * 32 * 6; i += 256) {
            int p = 98 + (i % 6);
            int d = (i / 6) % 32;
            int h = i / 192;
            VT32[h * 3456 + d * PST + p] = 0;
        }
    }

    const int px    = tid & 63;
    const int head  = tid >> 6;
    const int py    = px >> 3;
    const int pxx   = px & 7;
    const int y     = Y + py;
    const int x     = X + pxx;
    const int pixel = (b * 64 + y) * 64 + x;

    const int sh = min(max(y - 3, 0), 57);
    const int sw = min(max(x - 3, 0), 57);
    const int ry = sh - hb;
    const int rx = sw - wb;
    const int bias_base = head * 169 + (sh - y + 6) * 13 + (sw - x + 6);

    uint32_t qw[16];
    {
        const uint4* gq4 = (const uint4*)g_qh;
        #pragma unroll
        for (int j = 0; j < 4; j++) {
            uint4 v = gq4[pixel * 16 + head * 4 + j];
            qw[j * 4 + 0] = v.x; qw[j * 4 + 1] = v.y;
            qw[j * 4 + 2] = v.z; qw[j * 4 + 3] = v.w;
        }
    }
    __syncthreads();

    // ---- Pass 1: scores via HFMA2
    float s[49];
    #pragma unroll
    for (int iy = 0; iy < 7; iy++) {
        #pragma unroll
        for (int ix = 0; ix < 7; ix++) {
            int nb = (ry + iy) * 14 + (rx + ix);
            const uint4* kp4 = (const uint4*)&smn[nb * 68 + head * 16];
            __half2 a0 = __float2half2_rn(0.f), a1 = a0, a2 = a0, a3 = a0;
            #pragma unroll
            for (int j = 0; j < 4; j++) {
                uint4 kv = kp4[j];
                a0 = __hfma2(as_h2(qw[j * 4 + 0]), as_h2(kv.x), a0);
                a1 = __hfma2(as_h2(qw[j * 4 + 1]), as_h2(kv.y), a1);
                a2 = __hfma2(as_h2(qw[j * 4 + 2]), as_h2(kv.z), a2);
                a3 = __hfma2(as_h2(qw[j * 4 + 3]), as_h2(kv.w), a3);
            }
            a0 = __hadd2(a0, a1);
            a2 = __hadd2(a2, a3);
            float2 f = __half22float2(__hadd2(a0, a2));
            s[iy * 7 + ix] = f.x + f.y + __ldg(&rpb[bias_base + iy * 13 + ix]);
        }
    }

    // softmax (registers) + publish inv_l
    float m = s[0];
    #pragma unroll
    for (int i = 1; i < 49; i++) m = fmaxf(m, s[i]);
    float l = 0.f;
    #pragma unroll
    for (int i = 0; i < 49; i++) { s[i] = __expf(s[i] - m); l += s[i]; }
    l_s[head * 64 + px] = 1.0f / l;

    __syncthreads();   // K reads done; region1 becomes P/AT

    // ---- Zero P once (windows head-invariant: slots reused every round)
    #pragma unroll
    for (int i = 0; i < 27; i++) P32[tid + i * 256] = 0;

    // AV warp mapping
    const int lane = tid & 31;
    const int wrp  = tid >> 5;
    const int g    = lane >> 2;
    const int t    = lane & 3;
    const int wm2  = wrp >> 1;      // px m16-tile 0..3
    const int nh   = wrp & 1;       // 16-dim half
    const int r0   = wm2 * 16 + g;

    const int rodd = rx & 1;        // window-column parity (same for all rows)

    // ---- Per-head AV rounds
    #pragma unroll
    for (int h = 0; h < 4; h++) {
        __syncthreads();    // P free (zero-init or previous round's mma done)
        if (head == h) {
            // whole-u32 half2 stores; boundary slot explicitly zero
            #pragma unroll
            for (int iy = 0; iy < 7; iy++) {
                int w0 = (ry + iy) * 14 + rx;
                int p0 = w0 >> 1;
                const float* sr = &s[iy * 7];
                uint32_t u0, u1, u2, u3;
                if (!rodd) {
                    u0 = packh2(sr[0], sr[1]);
                    u1 = packh2(sr[2], sr[3]);
                    u2 = packh2(sr[4], sr[5]);
                    u3 = packh2(sr[6], 0.f);
                } else {
                    u0 = packh2(0.f, sr[0]);
                    u1 = packh2(sr[1], sr[2]);
                    u2 = packh2(sr[3], sr[4]);
                    u3 = packh2(sr[5], sr[6]);
                }
                P32[px * PST + p0 + 0] = u0;
                P32[px * PST + p0 + 1] = u1;
                P32[px * PST + p0 + 2] = u2;
                P32[px * PST + p0 + 3] = u3;
            }
        }
        __syncthreads();    // P ready

        float av[2][4];
        #pragma unroll
        for (int ni = 0; ni < 2; ni++)
            #pragma unroll
            for (int c = 0; c < 4; c++) av[ni][c] = 0.f;

        #pragma unroll
        for (int ks = 0; ks < 13; ks++) {
            const int kp0 = ks * 8;
            uint32_t a[4];
            a[0] = P32[r0 * PST + kp0 + t];
            a[1] = P32[(r0 + 8) * PST + kp0 + t];
            a[2] = P32[r0 * PST + kp0 + 4 + t];
            a[3] = P32[(r0 + 8) * PST + kp0 + 4 + t];
            #pragma unroll
            for (int ni = 0; ni < 2; ni++) {
                int cb = nh * 16 + ni * 8;
                uint32_t b0 = VT32[h * 3456 + (cb + g) * PST + kp0 + t];
                uint32_t b1 = VT32[h * 3456 + (cb + g) * PST + kp0 + 4 + t];
                mma_f16(av[ni], a, b0, b1);
            }
        }

        // Pack normalized attout into AT (rows r0, r0+8; head h's 16 kpairs)
        float il0 = l_s[h * 64 + r0];
        float il1 = l_s[h * 64 + r0 + 8];
        #pragma unroll
        for (int ni = 0; ni < 2; ni++) {
            int kp = h * 16 + nh * 8 + ni * 4 + t;
            AT32[r0 * PA2 + kp]       = packh2(av[ni][0] * il0, av[ni][1] * il0);
            AT32[(r0 + 8) * PA2 + kp] = packh2(av[ni][2] * il1, av[ni][3] * il1);
        }
    }
    __syncthreads();   // AT complete, VT reads done

    // ---- Stage proj W into region2 (overwrites VT)
    {
        const uint4* wp4 = (const uint4*)g_wpack;
        uint4* Bp4 = (uint4*)BP32;
        #pragma unroll
        for (int i = 0; i < 8; i++) {
            int idx = tid + i * 256;
            int kp  = idx >> 5;
            int ng  = idx & 31;
            Bp4[kp * 34 + ng] = wp4[kp * 32 + ng];
        }
    }
    __syncthreads();

    // ---- Proj GEMM: out = AT(64x128) @ Wp(128x128) + b_proj
    {
        const int wm = wrp & 1;
        const int wn = wrp >> 1;

        float pacc[2][4][4];
        #pragma unroll
        for (int i = 0; i < 2; i++)
            #pragma unroll
            for (int j = 0; j < 4; j++)
                #pragma unroll
                for (int c = 0; c < 4; c++) pacc[i][j][c] = 0.f;

        #pragma unroll
        for (int ks = 0; ks < 8; ks++) {
            const int kp0 = ks * 8;
            uint32_t a[2][4];
            #pragma unroll
            for (int mi = 0; mi < 2; mi++) {
                int rb = wm * 32 + mi * 16;
                a[mi][0] = AT32[(rb + g)     * PA2 + kp0 + t];
                a[mi][1] = AT32[(rb + g + 8) * PA2 + kp0 + t];
                a[mi][2] = AT32[(rb + g)     * PA2 + kp0 + 4 + t];
                a[mi][3] = AT32[(rb + g + 8) * PA2 + kp0 + 4 + t];
            }
            #pragma unroll
            for (int ni = 0; ni < 4; ni++) {
                int cb = wn * 32 + ni * 8;
                uint32_t b0 = BP32[(kp0 + t)     * PB2 + cb + g];
                uint32_t b1 = BP32[(kp0 + 4 + t) * PB2 + cb + g];
                mma_f16(pacc[0][ni], a[0], b0, b1);
                mma_f16(pacc[1][ni], a[1], b0, b1);
            }
        }

        #pragma unroll
        for (int ni = 0; ni < 4; ni++) {
            int c  = wn * 32 + ni * 8 + t * 2;
            float b0 = __ldg(&b_proj[c]);
            float b1 = __ldg(&b_proj[c + 1]);
            #pragma unroll
            for (int mi = 0; mi < 2; mi++) {
                int r = wm * 32 + mi * 16 + g;
                int p0 = (b * 64 + Y + (r >> 3)) * 64 + X + (r & 7);
                int r1 = r + 8;
                int p1 = (b * 64 + Y + (r1 >> 3)) * 64 + X + (r1 & 7);
                *(float2*)&out[(size_t)p0 * 128 + c] =
                    make_float2(pacc[mi][ni][0] + b0, pacc[mi][ni][1] + b1);
                *(float2*)&out[(size_t)p1 * 128 + c] =
                    make_float2(pacc[mi][ni][2] + b0, pacc[mi][ni][3] + b1);
            }
        }
    }
}

// ---------------------------------------------------------------------------
extern "C" void kernel_launch(void* const* d_in, const int* in_sizes, int n_in,
                              void* d_out, int out_size)
{
    const float* x      = (const float*)d_in[0];
    const float* w_qkv  = (const float*)d_in[1];
    const float* b_qkv  = (const float*)d_in[2];
    const float* rpb    = (const float*)d_in[3];
    const float* w_proj = (const float*)d_in[4];
    const float* b_proj = (const float*)d_in[5];
    float* out = (float*)d_out;

    cudaFuncSetAttribute(natten_proj_kernel,
                         cudaFuncAttributeMaxDynamicSharedMemorySize, NAT_SMEM);
    cudaFuncSetAttribute(gemm_qkv,
                         cudaFuncAttributeMaxDynamicSharedMemorySize, QKV_SMEM);

    gemm_qkv<<<257, 256, QKV_SMEM>>>(x, w_qkv, w_proj, b_qkv);
    natten_proj_kernel<<<256, 256, NAT_SMEM>>>(rpb, b_proj, out);
}